// round 11
// baseline (speedup 1.0000x reference)
#include <cuda_runtime.h>
#include <math_constants.h>

#define NN       8192
#define IN_DIM   200
#define DD       64
#define BM       128
#define BN       64
#define NT       256
#define STRK     72          // K stride (floats); 288 B, 16B multiple
#define STRV     68          // V stride (floats); 272 B, 16B multiple
#define SPLITS   4
#define STAGES   3
#define NEG_BIG  (-1.0e9f)

// stage block: [K 64*72][V 64*68][A 256 words]  = 9216 floats = 36864 B
#define SK_F     (BN * STRK)                 // 4608 floats
#define SV_F     (DD * STRV)                 // 4352 floats
#define SSZ_F    (SK_F + SV_F + 256)         // 9216 floats
#define SSZ_B    (SSZ_F * 4)                 // 36864 bytes

// Scratch (all __device__ globals; no allocations)
__device__ float    g_Hq[NN * DD];             // Q: [row][perm(d)]            tf32
__device__ float    g_Hk[NN * DD];             // K: [tile][krow][perm(d)]     tf32
__device__ float    g_Hv[NN * DD];             // V: [tile][d][perm(key)^swz]  tf32
__device__ unsigned g_Ab[NN * (NN / 32)];      // adjacency bitmask
__device__ float    g_Op[SPLITS * NN * DD];
__device__ float    g_mp[SPLITS * NN];
__device__ float    g_lp[SPLITS * NN];

// ---------------------------------------------------------------------------
__device__ __forceinline__ unsigned f2tf32(float f) {
    unsigned r;
    asm("cvt.rna.tf32.f32 %0, %1;" : "=r"(r) : "f"(f));
    return r;
}
__device__ __forceinline__ int perm8(int j) { return ((j & 3) << 1) | (j >> 2); }
__device__ __forceinline__ int perm (int j) { return (j & ~7) | perm8(j & 7); }

__device__ __forceinline__ void mma_tf32(float c[4],
                                         unsigned a0, unsigned a1,
                                         unsigned a2, unsigned a3,
                                         unsigned b0, unsigned b1) {
    asm volatile(
        "mma.sync.aligned.m16n8k8.row.col.f32.tf32.tf32.f32 "
        "{%0,%1,%2,%3}, {%4,%5,%6,%7}, {%8,%9}, {%0,%1,%2,%3};"
        : "+f"(c[0]), "+f"(c[1]), "+f"(c[2]), "+f"(c[3])
        : "r"(a0), "r"(a1), "r"(a2), "r"(a3), "r"(b0), "r"(b1));
}

__device__ __forceinline__ void cpa16(unsigned d, const void* s) {
    asm volatile("cp.async.cg.shared.global [%0], [%1], 16;" :: "r"(d), "l"(s));
}
__device__ __forceinline__ void cpa8(unsigned d, const void* s) {
    asm volatile("cp.async.ca.shared.global [%0], [%1], 8;" :: "r"(d), "l"(s));
}
__device__ __forceinline__ void cpa_commit() {
    asm volatile("cp.async.commit_group;" ::: "memory");
}
template <int N>
__device__ __forceinline__ void cpa_wait() {
    asm volatile("cp.async.wait_group %0;" :: "n"(N) : "memory");
}

// ---------------------------------------------------------------------------
// Kernel 1: H = X @ W + b, tf32-rounded into the three flash layouts.
// ---------------------------------------------------------------------------
__global__ void h_kernel(const float* __restrict__ X,
                         const float* __restrict__ W,
                         const float* __restrict__ b) {
    __shared__ float sx[8 * IN_DIM];
    const int tid  = threadIdx.x;
    const int rowq = blockIdx.x * 8;
    for (int i = tid; i < 8 * IN_DIM; i += 256)
        sx[i] = X[(size_t)rowq * IN_DIM + i];
    __syncthreads();
    const int r = tid >> 6, d = tid & 63;
    const float* x0 = sx + r * IN_DIM;
    const float* x1 = sx + (r + 4) * IN_DIM;
    float acc0 = b[d], acc1 = acc0;
#pragma unroll 8
    for (int k = 0; k < IN_DIM; k++) {
        float wv = W[k * DD + d];
        acc0 = fmaf(x0[k], wv, acc0);
        acc1 = fmaf(x1[k], wv, acc1);
    }
    const int pd = perm(d);
#pragma unroll
    for (int rr = 0; rr < 2; rr++) {
        int   row = rowq + r + rr * 4;
        float val = __uint_as_float(f2tf32(rr ? acc1 : acc0));
        int   t   = row >> 6, key = row & 63;
        int   krow = (key & ~7) | perm8(key & 7);
        g_Hq[row * DD + pd] = val;
        g_Hk[t * (BN * DD) + krow * DD + pd] = val;
        g_Hv[t * (BN * DD) + d * DD + (perm(key) ^ ((d & 7) << 3))] = val;
    }
}

// ---------------------------------------------------------------------------
// Kernel 1b: pack adjacency into bitmask (the mandatory DRAM stream).
// ---------------------------------------------------------------------------
__global__ void apack_kernel(const int* __restrict__ A) {
    const int row  = blockIdx.x;
    const int word = threadIdx.x;
    const int4* p  = (const int4*)(A + (size_t)row * NN + word * 32);
    unsigned bits = 0;
#pragma unroll
    for (int j = 0; j < 8; j++) {
        int4 v = p[j];
        bits |= (v.x > 0 ? 1u << (4 * j)     : 0u)
              | (v.y > 0 ? 1u << (4 * j + 1) : 0u)
              | (v.z > 0 ? 1u << (4 * j + 2) : 0u)
              | (v.w > 0 ? 1u << (4 * j + 3) : 0u);
    }
    g_Ab[row * 256 + word] = bits;
}

// ---------------------------------------------------------------------------
// Kernel 2: split-K flash attention; 3-stage cp.async pipeline, ONE barrier
// per tile; Q fragments in registers; online softmax; P stays in registers.
// ---------------------------------------------------------------------------
__global__ __launch_bounds__(NT, 2)
void flash_mma() {
    extern __shared__ float sm[];
    const unsigned smb = (unsigned)__cvta_generic_to_shared(sm);

    const int tid   = threadIdx.x;
    const int lane  = tid & 31;
    const int w     = tid >> 5;
    const int lr    = lane >> 2;
    const int lc    = lane & 3;
    const int split = blockIdx.x >> 6;           // 0..3
    const int qt    = blockIdx.x & 63;
    const int qbase = qt * BM;
    const int t0    = split * 32;
    const int t1    = t0 + 32;

    const int lrow0 = w * 16 + lr;
    const int r0    = qbase + lrow0;

    // staging chunk map: thread covers rows srow,+16,+32,+48, floats sj4..+3
    const int srow = tid >> 4;
    const int sj4  = (tid & 15) * 4;

    // ---- prologue: issue tiles t0 -> stage0, t0+1 -> stage1 ----
#pragma unroll
    for (int ps = 0; ps < 2; ps++) {
        const unsigned kb = smb + ps * SSZ_B;
        const unsigned vb = kb + SK_F * 4;
        const float* gk = &g_Hk[(size_t)(t0 + ps) * BN * DD];
        const float* gv = &g_Hv[(size_t)(t0 + ps) * BN * DD];
#pragma unroll
        for (int ii = 0; ii < 4; ii++) {
            int row = srow + ii * 16;
            cpa16(kb + (row * STRK + sj4) * 4, gk + row * DD + sj4);
            cpa16(vb + (row * STRV + sj4) * 4, gv + row * DD + sj4);
        }
        if (tid < BM)
            cpa8(kb + (SK_F + SV_F) * 4 + tid * 8,
                 &g_Ab[(size_t)(qbase + tid) * 256 + (t0 + ps) * 2]);
        cpa_commit();
    }

    // ---- Q fragments in registers (overlaps with cp.async in flight) ----
    unsigned aQ[8][4];
#pragma unroll
    for (int ks = 0; ks < 8; ks++) {
        float2 qa = *(const float2*)&g_Hq[(size_t)r0 * DD + ks * 8 + 2 * lc];
        float2 qb = *(const float2*)&g_Hq[(size_t)(r0 + 8) * DD + ks * 8 + 2 * lc];
        aQ[ks][0] = __float_as_uint(qa.x);
        aQ[ks][1] = __float_as_uint(qb.x);
        aQ[ks][2] = __float_as_uint(qa.y);
        aQ[ks][3] = __float_as_uint(qb.y);
    }

    float oc[8][4];
#pragma unroll
    for (int na = 0; na < 8; na++)
#pragma unroll
        for (int j = 0; j < 4; j++) oc[na][j] = 0.0f;
    float m0 = -CUDART_INF_F, m1 = -CUDART_INF_F;
    float l0 = 0.0f, l1 = 0.0f;

    for (int t = t0; t < t1; t++) {
        const int s  = (t - t0) % STAGES;         // read stage
        const int ws = (s + 2) % STAGES;          // write stage (free)

        cpa_wait<1>();       // tile t's group complete (own copies)
        __syncthreads();     // everyone's waits done -> tile t fully visible;
                             // everyone finished compute(t-1) -> stage ws free

        // ---- refill stage ws with tile t+2 (overlaps with compute below) ----
        if (t + 2 < t1) {
            const unsigned kb = smb + ws * SSZ_B;
            const unsigned vb = kb + SK_F * 4;
            const float* gk = &g_Hk[(size_t)(t + 2) * BN * DD];
            const float* gv = &g_Hv[(size_t)(t + 2) * BN * DD];
#pragma unroll
            for (int ii = 0; ii < 4; ii++) {
                int row = srow + ii * 16;
                cpa16(kb + (row * STRK + sj4) * 4, gk + row * DD + sj4);
                cpa16(vb + (row * STRV + sj4) * 4, gv + row * DD + sj4);
            }
            if (tid < BM)
                cpa8(kb + (SK_F + SV_F) * 4 + tid * 8,
                     &g_Ab[(size_t)(qbase + tid) * 256 + (t + 2) * 2]);
        }
        cpa_commit();        // commit (possibly empty) to keep group count

        const float*    cK = sm + s * SSZ_F;
        const float*    cV = cK + SK_F;
        const unsigned* cA = (const unsigned*)(cV + SV_F);

        // ---- S = Q K^T ----
        float sc[8][4];
#pragma unroll
        for (int na = 0; na < 8; na++)
#pragma unroll
            for (int j = 0; j < 4; j++) sc[na][j] = 0.0f;
#pragma unroll
        for (int ks = 0; ks < 8; ks++) {
#pragma unroll
            for (int na = 0; na < 8; na++) {
                float2 bf = *(const float2*)&cK[(na * 8 + lr) * STRK + ks * 8 + 2 * lc];
                mma_tf32(sc[na], aQ[ks][0], aQ[ks][1], aQ[ks][2], aQ[ks][3],
                         __float_as_uint(bf.x), __float_as_uint(bf.y));
            }
        }

        // ---- mask to NEG_BIG ----
        {
            unsigned b0w0 = cA[lrow0 * 2];
            unsigned b0w1 = cA[lrow0 * 2 + 1];
            unsigned b1w0 = cA[(lrow0 + 8) * 2];
            unsigned b1w1 = cA[(lrow0 + 8) * 2 + 1];
#pragma unroll
            for (int na = 0; na < 8; na++) {
                unsigned m0w = (na < 4) ? b0w0 : b0w1;
                unsigned m1w = (na < 4) ? b1w0 : b1w1;
                int sh = ((na & 3) << 3) + lc;
                sc[na][0] = ((m0w >> sh)       & 1) ? sc[na][0] : NEG_BIG;
                sc[na][1] = ((m0w >> (sh + 4)) & 1) ? sc[na][1] : NEG_BIG;
                sc[na][2] = ((m1w >> sh)       & 1) ? sc[na][2] : NEG_BIG;
                sc[na][3] = ((m1w >> (sh + 4)) & 1) ? sc[na][3] : NEG_BIG;
            }
        }

        // ---- online softmax; sc becomes the P A-fragments in place ----
        {
            float mt0 = NEG_BIG, mt1 = NEG_BIG;
#pragma unroll
            for (int na = 0; na < 8; na++) {
                mt0 = fmaxf(mt0, fmaxf(sc[na][0], sc[na][1]));
                mt1 = fmaxf(mt1, fmaxf(sc[na][2], sc[na][3]));
            }
            mt0 = fmaxf(mt0, __shfl_xor_sync(0xffffffffu, mt0, 1));
            mt0 = fmaxf(mt0, __shfl_xor_sync(0xffffffffu, mt0, 2));
            mt1 = fmaxf(mt1, __shfl_xor_sync(0xffffffffu, mt1, 1));
            mt1 = fmaxf(mt1, __shfl_xor_sync(0xffffffffu, mt1, 2));

            float mn0 = fmaxf(m0, mt0), mn1 = fmaxf(m1, mt1);
            float scl0 = __expf(m0 - mn0), scl1 = __expf(m1 - mn1);
            m0 = mn0; m1 = mn1;

            float s0 = 0.0f, s1 = 0.0f;
#pragma unroll
            for (int na = 0; na < 8; na++) {
                float p00 = __expf(sc[na][0] - m0);
                float p01 = __expf(sc[na][1] - m0);
                float p10 = __expf(sc[na][2] - m1);
                float p11 = __expf(sc[na][3] - m1);
                s0 += p00 + p01;
                s1 += p10 + p11;
                sc[na][0] = __uint_as_float(f2tf32(p00));
                sc[na][1] = __uint_as_float(f2tf32(p01));
                sc[na][2] = __uint_as_float(f2tf32(p10));
                sc[na][3] = __uint_as_float(f2tf32(p11));
            }
            s0 += __shfl_xor_sync(0xffffffffu, s0, 1);
            s0 += __shfl_xor_sync(0xffffffffu, s0, 2);
            s1 += __shfl_xor_sync(0xffffffffu, s1, 1);
            s1 += __shfl_xor_sync(0xffffffffu, s1, 2);
            l0 = l0 * scl0 + s0;
            l1 = l1 * scl1 + s1;

#pragma unroll
            for (int na = 0; na < 8; na++) {
                oc[na][0] *= scl0; oc[na][1] *= scl0;
                oc[na][2] *= scl1; oc[na][3] *= scl1;
            }
        }

        // ---- O += P V ----
#pragma unroll
        for (int ks = 0; ks < 8; ks++) {
            unsigned a0 = __float_as_uint(sc[ks][0]);
            unsigned a1 = __float_as_uint(sc[ks][2]);
            unsigned a2 = __float_as_uint(sc[ks][1]);
            unsigned a3 = __float_as_uint(sc[ks][3]);
#pragma unroll
            for (int na = 0; na < 8; na++) {
                float2 bf = *(const float2*)&cV[(na * 8 + lr) * STRV + (((ks ^ lr) << 3) + 2 * lc)];
                mma_tf32(oc[na], a0, a1, a2, a3,
                         __float_as_uint(bf.x), __float_as_uint(bf.y));
            }
        }
    }

    // ---- write partials ----
    float* Op = g_Op + (size_t)split * NN * DD;
#pragma unroll
    for (int na = 0; na < 8; na++) {
        int c0 = na * 8 + 2 * lc;
        *(float2*)&Op[(size_t)r0 * DD + c0]       = make_float2(oc[na][0], oc[na][1]);
        *(float2*)&Op[(size_t)(r0 + 8) * DD + c0] = make_float2(oc[na][2], oc[na][3]);
    }
    if (lc == 0) {
        g_mp[split * NN + r0]     = m0;
        g_mp[split * NN + r0 + 8] = m1;
        g_lp[split * NN + r0]     = l0;
        g_lp[split * NN + r0 + 8] = l1;
    }
}

// ---------------------------------------------------------------------------
// Kernel 3: m-aware merge (float4), normalize, relu.
// ---------------------------------------------------------------------------
__global__ void merge_kernel(float* __restrict__ Out) {
    int i4  = blockIdx.x * 256 + threadIdx.x;     // float4 index over NN*DD/4
    int idx = i4 * 4;
    int row = idx >> 6;
    float ma = g_mp[row], mb = g_mp[NN + row];
    float mc = g_mp[2 * NN + row], md = g_mp[3 * NN + row];
    float M = fmaxf(fmaxf(ma, mb), fmaxf(mc, md));
    float w0 = __expf(ma - M), w1 = __expf(mb - M);
    float w2 = __expf(mc - M), w3 = __expf(md - M);
    float inv = 1.0f / (w0 * g_lp[row] + w1 * g_lp[NN + row]
                      + w2 * g_lp[2 * NN + row] + w3 * g_lp[3 * NN + row]);
    float4 o0 = *(const float4*)&g_Op[idx];
    float4 o1 = *(const float4*)&g_Op[NN * DD + idx];
    float4 o2 = *(const float4*)&g_Op[2 * NN * DD + idx];
    float4 o3 = *(const float4*)&g_Op[3 * NN * DD + idx];
    float4 o;
    o.x = fmaxf((w0 * o0.x + w1 * o1.x + w2 * o2.x + w3 * o3.x) * inv, 0.0f);
    o.y = fmaxf((w0 * o0.y + w1 * o1.y + w2 * o2.y + w3 * o3.y) * inv, 0.0f);
    o.z = fmaxf((w0 * o0.z + w1 * o1.z + w2 * o2.z + w3 * o3.z) * inv, 0.0f);
    o.w = fmaxf((w0 * o0.w + w1 * o1.w + w2 * o2.w + w3 * o3.w) * inv, 0.0f);
    *(float4*)&Out[idx] = o;
}

// ---------------------------------------------------------------------------
extern "C" void kernel_launch(void* const* d_in, const int* in_sizes, int n_in,
                              void* d_out, int out_size) {
    const float* X = (const float*)d_in[0];
    const int*   A = (const int*)  d_in[1];
    const float* W = (const float*)d_in[2];
    const float* b = (const float*)d_in[3];
    float* Out = (float*)d_out;

    const int smem_bytes = STAGES * SSZ_B;        // 110592
    static bool attr_set = false;
    if (!attr_set) {
        cudaFuncSetAttribute(flash_mma,
                             cudaFuncAttributeMaxDynamicSharedMemorySize,
                             smem_bytes);
        attr_set = true;
    }

    h_kernel<<<NN / 8, 256>>>(X, W, b);
    apack_kernel<<<NN, 256>>>(A);
    flash_mma<<<SPLITS * 64, NT, smem_bytes>>>();
    merge_kernel<<<NN * DD / 4 / 256, 256>>>(Out);
}

// round 12
// speedup vs baseline: 1.4478x; 1.4478x over previous
#include <cuda_runtime.h>
#include <cuda_fp16.h>
#include <math_constants.h>

#define NN       8192
#define IN_DIM   200
#define DD       64
#define BM       128
#define BN       64
#define NT       256
#define SPLITS   4
#define STAGES   3
#define NEG_BIG  (-1.0e9f)

// fp16 stage: K 64x64 half (8192B) + V 64x64 half (8192B) + A 256 words (1024B)
#define KBYTES   8192
#define VBYTES   8192
#define SSZ_B    (KBYTES + VBYTES + 1024)     // 17408

// Scratch (all __device__ globals; no allocations)
__device__ __half   g_Hq[NN * DD];             // Q: [row][qpos(d)]
__device__ __half   g_Hk[NN * DD];             // K: [tile][key][kpos(d,key)]
__device__ __half   g_Hv[NN * DD];             // V: [tile][d][vpos(key,d)]
__device__ unsigned g_Ab[NN * (NN / 32)];      // adjacency bitmask
__device__ float    g_Op[SPLITS * NN * DD];
__device__ float    g_mp[SPLITS * NN];
__device__ float    g_lp[SPLITS * NN];

// ---------------------------------------------------------------------------
__device__ __forceinline__ int perm8(int j) { return ((j & 3) << 1) | (j >> 2); }

// half-position maps (slot = pair of elements; perm8 makes (j, j+4) adjacent
// so one LDS.64 yields the fp16 fragment's {x, x+8} pairs; block-XOR kills
// bank conflicts across the 8 rows read per mma)
__device__ __forceinline__ int qpos(int d) {
    return (d >> 4) * 16 + perm8((d >> 1) & 7) * 2 + (d & 1);
}
__device__ __forceinline__ int kpos(int d, int k) {
    return (((d >> 4) ^ (k & 3)) << 4) + perm8((d >> 1) & 7) * 2 + (d & 1);
}
__device__ __forceinline__ int vpos(int k, int d) {
    return (((k >> 4) ^ (d & 3)) << 4) + perm8((k >> 1) & 7) * 2 + (k & 1);
}

__device__ __forceinline__ unsigned packh2(float lo, float hi) {
    unsigned r;
    asm("cvt.rn.f16x2.f32 %0, %1, %2;" : "=r"(r) : "f"(hi), "f"(lo));
    return r;
}

__device__ __forceinline__ void mma_fp16(float c[4],
                                         unsigned a0, unsigned a1,
                                         unsigned a2, unsigned a3,
                                         unsigned b0, unsigned b1) {
    asm volatile(
        "mma.sync.aligned.m16n8k16.row.col.f32.f16.f16.f32 "
        "{%0,%1,%2,%3}, {%4,%5,%6,%7}, {%8,%9}, {%0,%1,%2,%3};"
        : "+f"(c[0]), "+f"(c[1]), "+f"(c[2]), "+f"(c[3])
        : "r"(a0), "r"(a1), "r"(a2), "r"(a3), "r"(b0), "r"(b1));
}

__device__ __forceinline__ void cpa16(unsigned d, const void* s) {
    asm volatile("cp.async.cg.shared.global [%0], [%1], 16;" :: "r"(d), "l"(s));
}
__device__ __forceinline__ void cpa8(unsigned d, const void* s) {
    asm volatile("cp.async.ca.shared.global [%0], [%1], 8;" :: "r"(d), "l"(s));
}
__device__ __forceinline__ void cpa_commit() {
    asm volatile("cp.async.commit_group;" ::: "memory");
}
template <int N>
__device__ __forceinline__ void cpa_wait() {
    asm volatile("cp.async.wait_group %0;" :: "n"(N) : "memory");
}

// ---------------------------------------------------------------------------
// Kernel 1: H = X @ W + b, fp16-rounded into the three flash layouts.
// ---------------------------------------------------------------------------
__global__ void h_kernel(const float* __restrict__ X,
                         const float* __restrict__ W,
                         const float* __restrict__ b) {
    __shared__ float sx[8 * IN_DIM];
    const int tid  = threadIdx.x;
    const int rowq = blockIdx.x * 8;
    for (int i = tid; i < 8 * IN_DIM; i += 256)
        sx[i] = X[(size_t)rowq * IN_DIM + i];
    __syncthreads();
    const int r = tid >> 6, d = tid & 63;
    const float* x0 = sx + r * IN_DIM;
    const float* x1 = sx + (r + 4) * IN_DIM;
    float acc0 = b[d], acc1 = acc0;
#pragma unroll 8
    for (int k = 0; k < IN_DIM; k++) {
        float wv = W[k * DD + d];
        acc0 = fmaf(x0[k], wv, acc0);
        acc1 = fmaf(x1[k], wv, acc1);
    }
#pragma unroll
    for (int rr = 0; rr < 2; rr++) {
        int    row = rowq + r + rr * 4;
        __half hv  = __float2half_rn(rr ? acc1 : acc0);
        int    t   = row >> 6, key = row & 63;
        g_Hq[row * DD + qpos(d)]                 = hv;
        g_Hk[t * (BN * DD) + key * DD + kpos(d, key)] = hv;
        g_Hv[t * (BN * DD) + d * DD + vpos(key, d)]   = hv;
    }
}

// ---------------------------------------------------------------------------
// Kernel 1b: pack adjacency into bitmask (the mandatory DRAM stream).
// ---------------------------------------------------------------------------
__global__ void apack_kernel(const int* __restrict__ A) {
    const int row  = blockIdx.x;
    const int word = threadIdx.x;
    const int4* p  = (const int4*)(A + (size_t)row * NN + word * 32);
    unsigned bits = 0;
#pragma unroll
    for (int j = 0; j < 8; j++) {
        int4 v = p[j];
        bits |= (v.x > 0 ? 1u << (4 * j)     : 0u)
              | (v.y > 0 ? 1u << (4 * j + 1) : 0u)
              | (v.z > 0 ? 1u << (4 * j + 2) : 0u)
              | (v.w > 0 ? 1u << (4 * j + 3) : 0u);
    }
    g_Ab[row * 256 + word] = bits;
}

// ---------------------------------------------------------------------------
// Kernel 2: split-K flash attention on fp16 m16n8k16; 3-stage cp.async
// pipeline, ONE barrier per tile; Q frags in registers (16 regs);
// S C-frags feed the O-mma A-frags natively (just f16x2 packs).
// ---------------------------------------------------------------------------
__global__ __launch_bounds__(NT, 2)
void flash_mma() {
    extern __shared__ char sm[];
    const unsigned smb = (unsigned)__cvta_generic_to_shared(sm);

    const int tid   = threadIdx.x;
    const int lane  = tid & 31;
    const int lr    = lane >> 2;
    const int lrm   = lr & 3;
    const int lc    = lane & 3;
    const int w     = tid >> 5;
    const int split = blockIdx.x >> 6;           // 0..3
    const int qt    = blockIdx.x & 63;
    const int qbase = qt * BM;
    const int t0    = split * 32;
    const int t1    = t0 + 32;

    const int lrow0 = w * 16 + lr;
    const int r0    = qbase + lrow0;

    // ---- prologue: issue tiles t0 -> stage0, t0+1 -> stage1 ----
#pragma unroll
    for (int ps = 0; ps < 2; ps++) {
        const unsigned base = smb + ps * SSZ_B;
        const char* gk = (const char*)g_Hk + (size_t)(t0 + ps) * KBYTES;
        const char* gv = (const char*)g_Hv + (size_t)(t0 + ps) * VBYTES;
        cpa16(base + tid * 16,                  gk + tid * 16);
        cpa16(base + (tid + NT) * 16,           gk + (tid + NT) * 16);
        cpa16(base + KBYTES + tid * 16,         gv + tid * 16);
        cpa16(base + KBYTES + (tid + NT) * 16,  gv + (tid + NT) * 16);
        if (tid < BM)
            cpa8(base + KBYTES + VBYTES + tid * 8,
                 &g_Ab[(size_t)(qbase + tid) * 256 + (t0 + ps) * 2]);
        cpa_commit();
    }

    // ---- Q fragments in registers: 4 k-steps x 4 regs = 16 regs ----
    unsigned aQ[4][4];
#pragma unroll
    for (int ks = 0; ks < 4; ks++) {
        uint2 qa = *(const uint2*)((const char*)g_Hq + ((size_t)r0 * DD + ks * 16 + 4 * lc) * 2);
        uint2 qb = *(const uint2*)((const char*)g_Hq + ((size_t)(r0 + 8) * DD + ks * 16 + 4 * lc) * 2);
        aQ[ks][0] = qa.x;   // (row lr,   dims 16ks+2lc..+1)
        aQ[ks][1] = qb.x;   // (row lr+8, same)
        aQ[ks][2] = qa.y;   // (row lr,   dims 16ks+8+2lc..+1)
        aQ[ks][3] = qb.y;
    }

    float oc[8][4];
#pragma unroll
    for (int na = 0; na < 8; na++)
#pragma unroll
        for (int j = 0; j < 4; j++) oc[na][j] = 0.0f;
    float m0 = -CUDART_INF_F, m1 = -CUDART_INF_F;
    float l0 = 0.0f, l1 = 0.0f;

    for (int t = t0; t < t1; t++) {
        const int s  = (t - t0) % STAGES;
        const int ws = (s + 2) % STAGES;

        cpa_wait<1>();       // tile t's group complete (own copies)
        __syncthreads();     // tile t visible to all; stage ws free

        // ---- refill stage ws with tile t+2 (overlaps compute) ----
        if (t + 2 < t1) {
            const unsigned base = smb + ws * SSZ_B;
            const char* gk = (const char*)g_Hk + (size_t)(t + 2) * KBYTES;
            const char* gv = (const char*)g_Hv + (size_t)(t + 2) * VBYTES;
            cpa16(base + tid * 16,                  gk + tid * 16);
            cpa16(base + (tid + NT) * 16,           gk + (tid + NT) * 16);
            cpa16(base + KBYTES + tid * 16,         gv + tid * 16);
            cpa16(base + KBYTES + (tid + NT) * 16,  gv + (tid + NT) * 16);
            if (tid < BM)
                cpa8(base + KBYTES + VBYTES + tid * 8,
                     &g_Ab[(size_t)(qbase + tid) * 256 + (t + 2) * 2]);
        }
        cpa_commit();

        const char*     cK = sm + s * SSZ_B;
        const char*     cV = cK + KBYTES;
        const unsigned* cA = (const unsigned*)(cV + VBYTES);

        // ---- S = Q K^T (fp16, 4 k-steps) ----
        float sc[8][4];
#pragma unroll
        for (int na = 0; na < 8; na++)
#pragma unroll
            for (int j = 0; j < 4; j++) sc[na][j] = 0.0f;
#pragma unroll
        for (int ks = 0; ks < 4; ks++) {
#pragma unroll
            for (int na = 0; na < 8; na++) {
                uint2 bk = *(const uint2*)(cK + (((na * 8 + lr) * DD
                              + ((ks ^ lrm) << 4) + 4 * lc) * 2));
                mma_fp16(sc[na], aQ[ks][0], aQ[ks][1], aQ[ks][2], aQ[ks][3],
                         bk.x, bk.y);
            }
        }

        // ---- mask to NEG_BIG ----
        // sc[na][0]=(lr, key na*8+2lc) [1]=+1  [2]=(lr+8, key) [3]=+1
        {
            unsigned b0w0 = cA[lrow0 * 2];
            unsigned b0w1 = cA[lrow0 * 2 + 1];
            unsigned b1w0 = cA[(lrow0 + 8) * 2];
            unsigned b1w1 = cA[(lrow0 + 8) * 2 + 1];
#pragma unroll
            for (int na = 0; na < 8; na++) {
                unsigned m0w = (na < 4) ? b0w0 : b0w1;
                unsigned m1w = (na < 4) ? b1w0 : b1w1;
                int sh = ((na & 3) << 3) + 2 * lc;
                sc[na][0] = ((m0w >> sh)       & 1) ? sc[na][0] : NEG_BIG;
                sc[na][1] = ((m0w >> (sh + 1)) & 1) ? sc[na][1] : NEG_BIG;
                sc[na][2] = ((m1w >> sh)       & 1) ? sc[na][2] : NEG_BIG;
                sc[na][3] = ((m1w >> (sh + 1)) & 1) ? sc[na][3] : NEG_BIG;
            }
        }

        // ---- online softmax (fp32) ----
        {
            float mt0 = NEG_BIG, mt1 = NEG_BIG;
#pragma unroll
            for (int na = 0; na < 8; na++) {
                mt0 = fmaxf(mt0, fmaxf(sc[na][0], sc[na][1]));
                mt1 = fmaxf(mt1, fmaxf(sc[na][2], sc[na][3]));
            }
            mt0 = fmaxf(mt0, __shfl_xor_sync(0xffffffffu, mt0, 1));
            mt0 = fmaxf(mt0, __shfl_xor_sync(0xffffffffu, mt0, 2));
            mt1 = fmaxf(mt1, __shfl_xor_sync(0xffffffffu, mt1, 1));
            mt1 = fmaxf(mt1, __shfl_xor_sync(0xffffffffu, mt1, 2));

            float mn0 = fmaxf(m0, mt0), mn1 = fmaxf(m1, mt1);
            float scl0 = __expf(m0 - mn0), scl1 = __expf(m1 - mn1);
            m0 = mn0; m1 = mn1;

            float s0 = 0.0f, s1 = 0.0f;
#pragma unroll
            for (int na = 0; na < 8; na++) {
                sc[na][0] = __expf(sc[na][0] - m0);
                sc[na][1] = __expf(sc[na][1] - m0);
                sc[na][2] = __expf(sc[na][2] - m1);
                sc[na][3] = __expf(sc[na][3] - m1);
                s0 += sc[na][0] + sc[na][1];
                s1 += sc[na][2] + sc[na][3];
            }
            s0 += __shfl_xor_sync(0xffffffffu, s0, 1);
            s0 += __shfl_xor_sync(0xffffffffu, s0, 2);
            s1 += __shfl_xor_sync(0xffffffffu, s1, 1);
            s1 += __shfl_xor_sync(0xffffffffu, s1, 2);
            l0 = l0 * scl0 + s0;
            l1 = l1 * scl1 + s1;

#pragma unroll
            for (int na = 0; na < 8; na++) {
                oc[na][0] *= scl0; oc[na][1] *= scl0;
                oc[na][2] *= scl1; oc[na][3] *= scl1;
            }
        }

        // ---- O += P V : S C-frags pack natively into fp16 A-frags ----
#pragma unroll
        for (int ks = 0; ks < 4; ks++) {
            unsigned a0 = packh2(sc[2 * ks][0],     sc[2 * ks][1]);
            unsigned a1 = packh2(sc[2 * ks][2],     sc[2 * ks][3]);
            unsigned a2 = packh2(sc[2 * ks + 1][0], sc[2 * ks + 1][1]);
            unsigned a3 = packh2(sc[2 * ks + 1][2], sc[2 * ks + 1][3]);
#pragma unroll
            for (int na = 0; na < 8; na++) {
                uint2 bv = *(const uint2*)(cV + (((na * 8 + lr) * DD
                              + ((ks ^ lrm) << 4) + 4 * lc) * 2));
                mma_fp16(oc[na], a0, a1, a2, a3, bv.x, bv.y);
            }
        }
    }

    // ---- write partials ----
    float* Op = g_Op + (size_t)split * NN * DD;
#pragma unroll
    for (int na = 0; na < 8; na++) {
        int c0 = na * 8 + 2 * lc;
        *(float2*)&Op[(size_t)r0 * DD + c0]       = make_float2(oc[na][0], oc[na][1]);
        *(float2*)&Op[(size_t)(r0 + 8) * DD + c0] = make_float2(oc[na][2], oc[na][3]);
    }
    if (lc == 0) {
        g_mp[split * NN + r0]     = m0;
        g_mp[split * NN + r0 + 8] = m1;
        g_lp[split * NN + r0]     = l0;
        g_lp[split * NN + r0 + 8] = l1;
    }
}

// ---------------------------------------------------------------------------
// Kernel 3: m-aware merge (float4), normalize, relu.
// ---------------------------------------------------------------------------
__global__ void merge_kernel(float* __restrict__ Out) {
    int i4  = blockIdx.x * 256 + threadIdx.x;
    int idx = i4 * 4;
    int row = idx >> 6;
    float ma = g_mp[row], mb = g_mp[NN + row];
    float mc = g_mp[2 * NN + row], md = g_mp[3 * NN + row];
    float M = fmaxf(fmaxf(ma, mb), fmaxf(mc, md));
    float w0 = __expf(ma - M), w1 = __expf(mb - M);
    float w2 = __expf(mc - M), w3 = __expf(md - M);
    float inv = 1.0f / (w0 * g_lp[row] + w1 * g_lp[NN + row]
                      + w2 * g_lp[2 * NN + row] + w3 * g_lp[3 * NN + row]);
    float4 o0 = *(const float4*)&g_Op[idx];
    float4 o1 = *(const float4*)&g_Op[NN * DD + idx];
    float4 o2 = *(const float4*)&g_Op[2 * NN * DD + idx];
    float4 o3 = *(const float4*)&g_Op[3 * NN * DD + idx];
    float4 o;
    o.x = fmaxf((w0 * o0.x + w1 * o1.x + w2 * o2.x + w3 * o3.x) * inv, 0.0f);
    o.y = fmaxf((w0 * o0.y + w1 * o1.y + w2 * o2.y + w3 * o3.y) * inv, 0.0f);
    o.z = fmaxf((w0 * o0.z + w1 * o1.z + w2 * o2.z + w3 * o3.z) * inv, 0.0f);
    o.w = fmaxf((w0 * o0.w + w1 * o1.w + w2 * o2.w + w3 * o3.w) * inv, 0.0f);
    *(float4*)&Out[idx] = o;
}

// ---------------------------------------------------------------------------
extern "C" void kernel_launch(void* const* d_in, const int* in_sizes, int n_in,
                              void* d_out, int out_size) {
    const float* X = (const float*)d_in[0];
    const int*   A = (const int*)  d_in[1];
    const float* W = (const float*)d_in[2];
    const float* b = (const float*)d_in[3];
    float* Out = (float*)d_out;

    const int smem_bytes = STAGES * SSZ_B;        // 52224
    static bool attr_set = false;
    if (!attr_set) {
        cudaFuncSetAttribute(flash_mma,
                             cudaFuncAttributeMaxDynamicSharedMemorySize,
                             smem_bytes);
        attr_set = true;
    }

    h_kernel<<<NN / 8, 256>>>(X, W, b);
    apack_kernel<<<NN, 256>>>(A);
    flash_mma<<<SPLITS * 64, NT, smem_bytes>>>();
    merge_kernel<<<NN * DD / 4 / 256, 256>>>(Out);
}

// round 13
// speedup vs baseline: 1.9685x; 1.3596x over previous
#include <cuda_runtime.h>
#include <cuda_fp16.h>
#include <math_constants.h>

#define NN       8192
#define IN_DIM   200
#define DD       64
#define BM       128
#define BN       64
#define NT       256
#define SPLITS   4
#define STAGES   2
#define NEG_BIG  (-1.0e9f)

// fp16 stage: K 64x64 half (8192B) + V 64x64 half (8192B) + A raw 128x64 int (32768B)
#define KBYTES   8192
#define VBYTES   8192
#define ABYTES   32768
#define SSZ_B    (KBYTES + VBYTES + ABYTES)   // 49152

// Scratch (all __device__ globals; no allocations)
__device__ __half   g_Hq[NN * DD];             // Q: [row][qpos(d)]
__device__ __half   g_Hk[NN * DD];             // K: [tile][key][kpos(d,key)]
__device__ __half   g_Hv[NN * DD];             // V: [tile][d][vpos(key,d)]
__device__ float    g_Op[SPLITS * NN * DD];
__device__ float    g_mp[SPLITS * NN];
__device__ float    g_lp[SPLITS * NN];

// ---------------------------------------------------------------------------
__device__ __forceinline__ int perm8(int j) { return ((j & 3) << 1) | (j >> 2); }

__device__ __forceinline__ int qpos(int d) {
    return (d >> 4) * 16 + perm8((d >> 1) & 7) * 2 + (d & 1);
}
__device__ __forceinline__ int kpos(int d, int k) {
    return (((d >> 4) ^ (k & 3)) << 4) + perm8((d >> 1) & 7) * 2 + (d & 1);
}
__device__ __forceinline__ int vpos(int k, int d) {
    return (((k >> 4) ^ (d & 3)) << 4) + perm8((k >> 1) & 7) * 2 + (k & 1);
}

__device__ __forceinline__ unsigned packh2(float lo, float hi) {
    unsigned r;
    asm("cvt.rn.f16x2.f32 %0, %1, %2;" : "=r"(r) : "f"(hi), "f"(lo));
    return r;
}

__device__ __forceinline__ void mma_fp16(float c[4],
                                         unsigned a0, unsigned a1,
                                         unsigned a2, unsigned a3,
                                         unsigned b0, unsigned b1) {
    asm volatile(
        "mma.sync.aligned.m16n8k16.row.col.f32.f16.f16.f32 "
        "{%0,%1,%2,%3}, {%4,%5,%6,%7}, {%8,%9}, {%0,%1,%2,%3};"
        : "+f"(c[0]), "+f"(c[1]), "+f"(c[2]), "+f"(c[3])
        : "r"(a0), "r"(a1), "r"(a2), "r"(a3), "r"(b0), "r"(b1));
}

__device__ __forceinline__ void cpa16(unsigned d, const void* s) {
    asm volatile("cp.async.cg.shared.global [%0], [%1], 16;" :: "r"(d), "l"(s));
}
__device__ __forceinline__ void cpa_commit() {
    asm volatile("cp.async.commit_group;" ::: "memory");
}
template <int N>
__device__ __forceinline__ void cpa_wait() {
    asm volatile("cp.async.wait_group %0;" :: "n"(N) : "memory");
}

// ---------------------------------------------------------------------------
// Kernel 1: H = X @ W + b, fp16-rounded into the three flash layouts.
// ---------------------------------------------------------------------------
__global__ void h_kernel(const float* __restrict__ X,
                         const float* __restrict__ W,
                         const float* __restrict__ b) {
    __shared__ float sx[8 * IN_DIM];
    const int tid  = threadIdx.x;
    const int rowq = blockIdx.x * 8;
    for (int i = tid; i < 8 * IN_DIM; i += 256)
        sx[i] = X[(size_t)rowq * IN_DIM + i];
    __syncthreads();
    const int r = tid >> 6, d = tid & 63;
    const float* x0 = sx + r * IN_DIM;
    const float* x1 = sx + (r + 4) * IN_DIM;
    float acc0 = b[d], acc1 = acc0;
#pragma unroll 8
    for (int k = 0; k < IN_DIM; k++) {
        float wv = W[k * DD + d];
        acc0 = fmaf(x0[k], wv, acc0);
        acc1 = fmaf(x1[k], wv, acc1);
    }
#pragma unroll
    for (int rr = 0; rr < 2; rr++) {
        int    row = rowq + r + rr * 4;
        __half hv  = __float2half_rn(rr ? acc1 : acc0);
        int    t   = row >> 6, key = row & 63;
        g_Hq[row * DD + qpos(d)]                      = hv;
        g_Hk[t * (BN * DD) + key * DD + kpos(d, key)] = hv;
        g_Hv[t * (BN * DD) + d * DD + vpos(key, d)]   = hv;
    }
}

// ---------------------------------------------------------------------------
// Kernel 2: split-K flash attention on fp16 m16n8k16. 2-stage cp.async
// pipeline streams K/V AND the raw adjacency tile (32 KB, XOR-swizzled at
// 16B-chunk granularity) so the mandatory 268 MB A read overlaps compute.
// ---------------------------------------------------------------------------
__global__ __launch_bounds__(NT, 2)
void flash_mma(const int* __restrict__ A) {
    extern __shared__ char sm[];
    const unsigned smb = (unsigned)__cvta_generic_to_shared(sm);

    const int tid   = threadIdx.x;
    const int lane  = tid & 31;
    const int lr    = lane >> 2;
    const int lrm   = lr & 3;
    const int lc    = lane & 3;
    const int w     = tid >> 5;
    const int split = blockIdx.x >> 6;           // 0..3
    const int qt    = blockIdx.x & 63;
    const int qbase = qt * BM;
    const int t0    = split * 32;
    const int t1    = t0 + 32;

    const int lrow0 = w * 16 + lr;
    const int r0    = qbase + lrow0;

    // A staging map: 2048 chunks of 16B; thread covers 8 chunks
    // chunk g: row = g>>4, c = g&15; stored at chunk (c ^ (row&15))
    // ---- prologue: issue tiles t0 -> stage0, t0+1 -> stage1 ----
#pragma unroll
    for (int ps = 0; ps < 2; ps++) {
        const unsigned base = smb + ps * SSZ_B;
        const char* gk = (const char*)g_Hk + (size_t)(t0 + ps) * KBYTES;
        const char* gv = (const char*)g_Hv + (size_t)(t0 + ps) * VBYTES;
        cpa16(base + tid * 16,                  gk + tid * 16);
        cpa16(base + (tid + NT) * 16,           gk + (tid + NT) * 16);
        cpa16(base + KBYTES + tid * 16,         gv + tid * 16);
        cpa16(base + KBYTES + (tid + NT) * 16,  gv + (tid + NT) * 16);
#pragma unroll
        for (int ii = 0; ii < 8; ii++) {
            int g = tid + ii * NT;
            int row = g >> 4, c = g & 15;
            cpa16(base + KBYTES + VBYTES + row * 256 + ((c ^ (row & 15)) << 4),
                  A + (size_t)(qbase + row) * NN + (t0 + ps) * BN + c * 4);
        }
        cpa_commit();
    }

    // ---- Q fragments in registers: 16 regs ----
    unsigned aQ[4][4];
#pragma unroll
    for (int ks = 0; ks < 4; ks++) {
        uint2 qa = *(const uint2*)((const char*)g_Hq + ((size_t)r0 * DD + ks * 16 + 4 * lc) * 2);
        uint2 qb = *(const uint2*)((const char*)g_Hq + ((size_t)(r0 + 8) * DD + ks * 16 + 4 * lc) * 2);
        aQ[ks][0] = qa.x;
        aQ[ks][1] = qb.x;
        aQ[ks][2] = qa.y;
        aQ[ks][3] = qb.y;
    }

    float oc[8][4];
#pragma unroll
    for (int na = 0; na < 8; na++)
#pragma unroll
        for (int j = 0; j < 4; j++) oc[na][j] = 0.0f;
    float m0 = -CUDART_INF_F, m1 = -CUDART_INF_F;
    float l0 = 0.0f, l1 = 0.0f;

    for (int t = t0; t < t1; t++) {
        const int s = (t - t0) & 1;

        cpa_wait<1>();       // tile t's group complete
        __syncthreads();     // visible to all threads

        const char* cK = sm + s * SSZ_B;
        const char* cV = cK + KBYTES;
        const int*  cA = (const int*)(cV + VBYTES);

        // ---- S = Q K^T (fp16, 4 k-steps) ----
        float sc[8][4];
#pragma unroll
        for (int na = 0; na < 8; na++)
#pragma unroll
            for (int j = 0; j < 4; j++) sc[na][j] = 0.0f;
#pragma unroll
        for (int ks = 0; ks < 4; ks++) {
#pragma unroll
            for (int na = 0; na < 8; na++) {
                uint2 bk = *(const uint2*)(cK + (((na * 8 + lr) * DD
                              + ((ks ^ lrm) << 4) + 4 * lc) * 2));
                mma_fp16(sc[na], aQ[ks][0], aQ[ks][1], aQ[ks][2], aQ[ks][3],
                         bk.x, bk.y);
            }
        }

        // ---- mask straight from swizzled raw A in smem ----
        // keys na*8+2lc, +1 -> chunk c = na*2+(lc>>1), int offset (lc&1)*2
        {
            const int x0 = lrow0 & 15, x1 = (lrow0 + 8) & 15;
            const int o  = (lc & 1) * 2;
#pragma unroll
            for (int na = 0; na < 8; na++) {
                int c = na * 2 + (lc >> 1);
                int2 a0 = *(const int2*)(cA + lrow0 * 64       + ((c ^ x0) << 2) + o);
                int2 a1 = *(const int2*)(cA + (lrow0 + 8) * 64 + ((c ^ x1) << 2) + o);
                sc[na][0] = (a0.x > 0) ? sc[na][0] : NEG_BIG;
                sc[na][1] = (a0.y > 0) ? sc[na][1] : NEG_BIG;
                sc[na][2] = (a1.x > 0) ? sc[na][2] : NEG_BIG;
                sc[na][3] = (a1.y > 0) ? sc[na][3] : NEG_BIG;
            }
        }

        // ---- online softmax (fp32) ----
        {
            float mt0 = NEG_BIG, mt1 = NEG_BIG;
#pragma unroll
            for (int na = 0; na < 8; na++) {
                mt0 = fmaxf(mt0, fmaxf(sc[na][0], sc[na][1]));
                mt1 = fmaxf(mt1, fmaxf(sc[na][2], sc[na][3]));
            }
            mt0 = fmaxf(mt0, __shfl_xor_sync(0xffffffffu, mt0, 1));
            mt0 = fmaxf(mt0, __shfl_xor_sync(0xffffffffu, mt0, 2));
            mt1 = fmaxf(mt1, __shfl_xor_sync(0xffffffffu, mt1, 1));
            mt1 = fmaxf(mt1, __shfl_xor_sync(0xffffffffu, mt1, 2));

            float mn0 = fmaxf(m0, mt0), mn1 = fmaxf(m1, mt1);
            float scl0 = __expf(m0 - mn0), scl1 = __expf(m1 - mn1);
            m0 = mn0; m1 = mn1;

            float s0 = 0.0f, s1 = 0.0f;
#pragma unroll
            for (int na = 0; na < 8; na++) {
                sc[na][0] = __expf(sc[na][0] - m0);
                sc[na][1] = __expf(sc[na][1] - m0);
                sc[na][2] = __expf(sc[na][2] - m1);
                sc[na][3] = __expf(sc[na][3] - m1);
                s0 += sc[na][0] + sc[na][1];
                s1 += sc[na][2] + sc[na][3];
            }
            s0 += __shfl_xor_sync(0xffffffffu, s0, 1);
            s0 += __shfl_xor_sync(0xffffffffu, s0, 2);
            s1 += __shfl_xor_sync(0xffffffffu, s1, 1);
            s1 += __shfl_xor_sync(0xffffffffu, s1, 2);
            l0 = l0 * scl0 + s0;
            l1 = l1 * scl1 + s1;

#pragma unroll
            for (int na = 0; na < 8; na++) {
                oc[na][0] *= scl0; oc[na][1] *= scl0;
                oc[na][2] *= scl1; oc[na][3] *= scl1;
            }
        }

        // ---- O += P V ----
#pragma unroll
        for (int ks = 0; ks < 4; ks++) {
            unsigned a0 = packh2(sc[2 * ks][0],     sc[2 * ks][1]);
            unsigned a1 = packh2(sc[2 * ks][2],     sc[2 * ks][3]);
            unsigned a2 = packh2(sc[2 * ks + 1][0], sc[2 * ks + 1][1]);
            unsigned a3 = packh2(sc[2 * ks + 1][2], sc[2 * ks + 1][3]);
#pragma unroll
            for (int na = 0; na < 8; na++) {
                uint2 bv = *(const uint2*)(cV + (((na * 8 + lr) * DD
                              + ((ks ^ lrm) << 4) + 4 * lc) * 2));
                mma_fp16(oc[na], a0, a1, a2, a3, bv.x, bv.y);
            }
        }

        __syncthreads();     // all reads of stage s finished

        // ---- refill stage s with tile t+2 ----
        if (t + 2 < t1) {
            const unsigned base = smb + s * SSZ_B;
            const char* gk = (const char*)g_Hk + (size_t)(t + 2) * KBYTES;
            const char* gv = (const char*)g_Hv + (size_t)(t + 2) * VBYTES;
            cpa16(base + tid * 16,                  gk + tid * 16);
            cpa16(base + (tid + NT) * 16,           gk + (tid + NT) * 16);
            cpa16(base + KBYTES + tid * 16,         gv + tid * 16);
            cpa16(base + KBYTES + (tid + NT) * 16,  gv + (tid + NT) * 16);
#pragma unroll
            for (int ii = 0; ii < 8; ii++) {
                int g = tid + ii * NT;
                int row = g >> 4, c = g & 15;
                cpa16(base + KBYTES + VBYTES + row * 256 + ((c ^ (row & 15)) << 4),
                      A + (size_t)(qbase + row) * NN + (t + 2) * BN + c * 4);
            }
        }
        cpa_commit();
    }

    // ---- write partials ----
    float* Op = g_Op + (size_t)split * NN * DD;
#pragma unroll
    for (int na = 0; na < 8; na++) {
        int c0 = na * 8 + 2 * lc;
        *(float2*)&Op[(size_t)r0 * DD + c0]       = make_float2(oc[na][0], oc[na][1]);
        *(float2*)&Op[(size_t)(r0 + 8) * DD + c0] = make_float2(oc[na][2], oc[na][3]);
    }
    if (lc == 0) {
        g_mp[split * NN + r0]     = m0;
        g_mp[split * NN + r0 + 8] = m1;
        g_lp[split * NN + r0]     = l0;
        g_lp[split * NN + r0 + 8] = l1;
    }
}

// ---------------------------------------------------------------------------
// Kernel 3: m-aware merge (float4), normalize, relu.
// ---------------------------------------------------------------------------
__global__ void merge_kernel(float* __restrict__ Out) {
    int i4  = blockIdx.x * 256 + threadIdx.x;
    int idx = i4 * 4;
    int row = idx >> 6;
    float ma = g_mp[row], mb = g_mp[NN + row];
    float mc = g_mp[2 * NN + row], md = g_mp[3 * NN + row];
    float M = fmaxf(fmaxf(ma, mb), fmaxf(mc, md));
    float w0 = __expf(ma - M), w1 = __expf(mb - M);
    float w2 = __expf(mc - M), w3 = __expf(md - M);
    float inv = 1.0f / (w0 * g_lp[row] + w1 * g_lp[NN + row]
                      + w2 * g_lp[2 * NN + row] + w3 * g_lp[3 * NN + row]);
    float4 o0 = *(const float4*)&g_Op[idx];
    float4 o1 = *(const float4*)&g_Op[NN * DD + idx];
    float4 o2 = *(const float4*)&g_Op[2 * NN * DD + idx];
    float4 o3 = *(const float4*)&g_Op[3 * NN * DD + idx];
    float4 o;
    o.x = fmaxf((w0 * o0.x + w1 * o1.x + w2 * o2.x + w3 * o3.x) * inv, 0.0f);
    o.y = fmaxf((w0 * o0.y + w1 * o1.y + w2 * o2.y + w3 * o3.y) * inv, 0.0f);
    o.z = fmaxf((w0 * o0.z + w1 * o1.z + w2 * o2.z + w3 * o3.z) * inv, 0.0f);
    o.w = fmaxf((w0 * o0.w + w1 * o1.w + w2 * o2.w + w3 * o3.w) * inv, 0.0f);
    *(float4*)&Out[idx] = o;
}

// ---------------------------------------------------------------------------
extern "C" void kernel_launch(void* const* d_in, const int* in_sizes, int n_in,
                              void* d_out, int out_size) {
    const float* X = (const float*)d_in[0];
    const int*   A = (const int*)  d_in[1];
    const float* W = (const float*)d_in[2];
    const float* b = (const float*)d_in[3];
    float* Out = (float*)d_out;

    const int smem_bytes = STAGES * SSZ_B;        // 98304
    static bool attr_set = false;
    if (!attr_set) {
        cudaFuncSetAttribute(flash_mma,
                             cudaFuncAttributeMaxDynamicSharedMemorySize,
                             smem_bytes);
        attr_set = true;
    }

    h_kernel<<<NN / 8, 256>>>(X, W, b);
    flash_mma<<<SPLITS * 64, NT, smem_bytes>>>(A);
    merge_kernel<<<NN * DD / 4 / 256, 256>>>(Out);
}

// round 15
// speedup vs baseline: 2.2072x; 1.1213x over previous
#include <cuda_runtime.h>
#include <cuda_fp16.h>
#include <math_constants.h>

#define NN       8192
#define IN_DIM   200
#define DD       64
#define BM       128
#define BN       64
#define NT       256
#define NSPLIT   5
#define STAGES   2
#define NEG_BIG  (-1.0e9f)

// fp16 stage: K 64x64 half (8192B) + V 64x64 half (8192B) + A raw 128x64 int (32768B)
#define KBYTES   8192
#define VBYTES   8192
#define ABYTES   32768
#define SSZ_B    (KBYTES + VBYTES + ABYTES)   // 49152

// Scratch (all __device__ globals; no allocations)
__device__ __half   g_Hq[NN * DD];             // Q: [row][qpos(d)]
__device__ __half   g_Hk[NN * DD];             // K: [tile][key][kpos(d,key)]
__device__ __half   g_Hv[NN * DD];             // V: [tile][d][vpos(key,d)]
__device__ float    g_Op[NSPLIT * NN * DD];
__device__ float    g_mp[NSPLIT * NN];
__device__ float    g_lp[NSPLIT * NN];

// ---------------------------------------------------------------------------
__device__ __forceinline__ int perm8(int j) { return ((j & 3) << 1) | (j >> 2); }

__device__ __forceinline__ int qpos(int d) {
    return (d >> 4) * 16 + perm8((d >> 1) & 7) * 2 + (d & 1);
}
__device__ __forceinline__ int kpos(int d, int k) {
    return (((d >> 4) ^ (k & 3)) << 4) + perm8((d >> 1) & 7) * 2 + (d & 1);
}
__device__ __forceinline__ int vpos(int k, int d) {
    return (((k >> 4) ^ (d & 3)) << 4) + perm8((k >> 1) & 7) * 2 + (k & 1);
}

__device__ __forceinline__ unsigned packh2(float lo, float hi) {
    unsigned r;
    asm("cvt.rn.f16x2.f32 %0, %1, %2;" : "=r"(r) : "f"(hi), "f"(lo));
    return r;
}

__device__ __forceinline__ void mma_fp16(float c[4],
                                         unsigned a0, unsigned a1,
                                         unsigned a2, unsigned a3,
                                         unsigned b0, unsigned b1) {
    asm volatile(
        "mma.sync.aligned.m16n8k16.row.col.f32.f16.f16.f32 "
        "{%0,%1,%2,%3}, {%4,%5,%6,%7}, {%8,%9}, {%0,%1,%2,%3};"
        : "+f"(c[0]), "+f"(c[1]), "+f"(c[2]), "+f"(c[3])
        : "r"(a0), "r"(a1), "r"(a2), "r"(a3), "r"(b0), "r"(b1));
}

__device__ __forceinline__ void cpa16(unsigned d, const void* s) {
    asm volatile("cp.async.cg.shared.global [%0], [%1], 16;" :: "r"(d), "l"(s));
}
__device__ __forceinline__ void cpa_commit() {
    asm volatile("cp.async.commit_group;" ::: "memory");
}
template <int N>
__device__ __forceinline__ void cpa_wait() {
    asm volatile("cp.async.wait_group %0;" :: "n"(N) : "memory");
}

// ---------------------------------------------------------------------------
// Kernel 1: H = X @ W + b, fp16-rounded into the three flash layouts.
// ---------------------------------------------------------------------------
__global__ void h_kernel(const float* __restrict__ X,
                         const float* __restrict__ W,
                         const float* __restrict__ b) {
    __shared__ float sx[8 * IN_DIM];
    const int tid  = threadIdx.x;
    const int rowq = blockIdx.x * 8;
    for (int i = tid; i < 8 * IN_DIM; i += 256)
        sx[i] = X[(size_t)rowq * IN_DIM + i];
    __syncthreads();
    const int r = tid >> 6, d = tid & 63;
    const float* x0 = sx + r * IN_DIM;
    const float* x1 = sx + (r + 4) * IN_DIM;
    float acc0 = b[d], acc1 = acc0;
#pragma unroll 8
    for (int k = 0; k < IN_DIM; k++) {
        float wv = W[k * DD + d];
        acc0 = fmaf(x0[k], wv, acc0);
        acc1 = fmaf(x1[k], wv, acc1);
    }
#pragma unroll
    for (int rr = 0; rr < 2; rr++) {
        int    row = rowq + r + rr * 4;
        __half hv  = __float2half_rn(rr ? acc1 : acc0);
        int    t   = row >> 6, key = row & 63;
        g_Hq[row * DD + qpos(d)]                      = hv;
        g_Hk[t * (BN * DD) + key * DD + kpos(d, key)] = hv;
        g_Hv[t * (BN * DD) + d * DD + vpos(key, d)]   = hv;
    }
}

// ---------------------------------------------------------------------------
// Kernel 2: split-K flash attention on fp16 m16n8k16. 2-stage cp.async
// pipeline streams K/V AND raw adjacency (A read overlaps compute).
// Grid = 296 = 2x148: q-tiles 0..39 have 5 splits {26,26,26,25,25},
// q-tiles 40..63 have 4 splits {32,32,32,32}; totals: 40*128 + 24*128 =
// 8192 tile-units. bids b and b+148 share an SM; ordering gives per-SM
// sums 52/57/58 against ideal 55.35.
// ---------------------------------------------------------------------------
__global__ __launch_bounds__(NT, 2)
void flash_mma(const int* __restrict__ A) {
    extern __shared__ char sm[];
    const unsigned smb = (unsigned)__cvta_generic_to_shared(sm);

    const int tid   = threadIdx.x;
    const int lane  = tid & 31;
    const int lr    = lane >> 2;
    const int lrm   = lr & 3;
    const int lc    = lane & 3;
    const int w     = tid >> 5;

    // ---- balanced work-unit decode (partitions [0,128) key tiles) ----
    int qt, si, t0, len;
    {
        const int b = blockIdx.x;
        if (b < 96) {                      // U32: qt 40..63, 4 splits of 32
            qt = 40 + (b >> 2); si = b & 3; t0 = si * 32; len = 32;
        } else if (b < 164) {              // U26 (part): j in [0,52) u [104,120)
            int j = (b < 148) ? (b - 96) : (104 + (b - 148));
            qt = j / 3; si = j % 3; t0 = si * 26; len = 26;
        } else if (b < 244) {              // U25: qt 0..39, splits 3,4
            int k = b - 164;
            qt = k >> 1; si = 3 + (k & 1); t0 = 78 + (k & 1) * 25; len = 25;
        } else {                           // U26 (rest): j in [52,104)
            int j = 52 + (b - 244);
            qt = j / 3; si = j % 3; t0 = si * 26; len = 26;
        }
    }
    const int qbase = qt * BM;
    const int t1    = t0 + len;

    const int lrow0 = w * 16 + lr;
    const int r0    = qbase + lrow0;

    // ---- prologue: issue tiles t0 -> stage0, t0+1 -> stage1 ----
#pragma unroll
    for (int ps = 0; ps < 2; ps++) {
        const unsigned base = smb + ps * SSZ_B;
        const char* gk = (const char*)g_Hk + (size_t)(t0 + ps) * KBYTES;
        const char* gv = (const char*)g_Hv + (size_t)(t0 + ps) * VBYTES;
        cpa16(base + tid * 16,                  gk + tid * 16);
        cpa16(base + (tid + NT) * 16,           gk + (tid + NT) * 16);
        cpa16(base + KBYTES + tid * 16,         gv + tid * 16);
        cpa16(base + KBYTES + (tid + NT) * 16,  gv + (tid + NT) * 16);
#pragma unroll
        for (int ii = 0; ii < 8; ii++) {
            int g = tid + ii * NT;
            int row = g >> 4, c = g & 15;
            cpa16(base + KBYTES + VBYTES + row * 256 + ((c ^ (row & 15)) << 4),
                  A + (size_t)(qbase + row) * NN + (t0 + ps) * BN + c * 4);
        }
        cpa_commit();
    }

    // ---- Q fragments in registers: 16 regs ----
    unsigned aQ[4][4];
#pragma unroll
    for (int ks = 0; ks < 4; ks++) {
        uint2 qa = *(const uint2*)((const char*)g_Hq + ((size_t)r0 * DD + ks * 16 + 4 * lc) * 2);
        uint2 qb = *(const uint2*)((const char*)g_Hq + ((size_t)(r0 + 8) * DD + ks * 16 + 4 * lc) * 2);
        aQ[ks][0] = qa.x;
        aQ[ks][1] = qb.x;
        aQ[ks][2] = qa.y;
        aQ[ks][3] = qb.y;
    }

    float oc[8][4];
#pragma unroll
    for (int na = 0; na < 8; na++)
#pragma unroll
        for (int j = 0; j < 4; j++) oc[na][j] = 0.0f;
    float m0 = -CUDART_INF_F, m1 = -CUDART_INF_F;
    float l0 = 0.0f, l1 = 0.0f;

    for (int t = t0; t < t1; t++) {
        const int s = (t - t0) & 1;

        cpa_wait<1>();       // tile t's group complete
        __syncthreads();     // visible to all threads

        const char* cK = sm + s * SSZ_B;
        const char* cV = cK + KBYTES;
        const int*  cA = (const int*)(cV + VBYTES);

        // ---- S = Q K^T (fp16, 4 k-steps) ----
        float sc[8][4];
#pragma unroll
        for (int na = 0; na < 8; na++)
#pragma unroll
            for (int j = 0; j < 4; j++) sc[na][j] = 0.0f;
#pragma unroll
        for (int ks = 0; ks < 4; ks++) {
#pragma unroll
            for (int na = 0; na < 8; na++) {
                uint2 bk = *(const uint2*)(cK + (((na * 8 + lr) * DD
                              + ((ks ^ lrm) << 4) + 4 * lc) * 2));
                mma_fp16(sc[na], aQ[ks][0], aQ[ks][1], aQ[ks][2], aQ[ks][3],
                         bk.x, bk.y);
            }
        }

        // ---- mask straight from swizzled raw A in smem ----
        {
            const int x0 = lrow0 & 15, x1 = (lrow0 + 8) & 15;
            const int o  = (lc & 1) * 2;
#pragma unroll
            for (int na = 0; na < 8; na++) {
                int c = na * 2 + (lc >> 1);
                int2 a0 = *(const int2*)(cA + lrow0 * 64       + ((c ^ x0) << 2) + o);
                int2 a1 = *(const int2*)(cA + (lrow0 + 8) * 64 + ((c ^ x1) << 2) + o);
                sc[na][0] = (a0.x > 0) ? sc[na][0] : NEG_BIG;
                sc[na][1] = (a0.y > 0) ? sc[na][1] : NEG_BIG;
                sc[na][2] = (a1.x > 0) ? sc[na][2] : NEG_BIG;
                sc[na][3] = (a1.y > 0) ? sc[na][3] : NEG_BIG;
            }
        }

        // ---- online softmax (fp32) ----
        {
            float mt0 = NEG_BIG, mt1 = NEG_BIG;
#pragma unroll
            for (int na = 0; na < 8; na++) {
                mt0 = fmaxf(mt0, fmaxf(sc[na][0], sc[na][1]));
                mt1 = fmaxf(mt1, fmaxf(sc[na][2], sc[na][3]));
            }
            mt0 = fmaxf(mt0, __shfl_xor_sync(0xffffffffu, mt0, 1));
            mt0 = fmaxf(mt0, __shfl_xor_sync(0xffffffffu, mt0, 2));
            mt1 = fmaxf(mt1, __shfl_xor_sync(0xffffffffu, mt1, 1));
            mt1 = fmaxf(mt1, __shfl_xor_sync(0xffffffffu, mt1, 2));

            float mn0 = fmaxf(m0, mt0), mn1 = fmaxf(m1, mt1);
            float scl0 = __expf(m0 - mn0), scl1 = __expf(m1 - mn1);
            m0 = mn0; m1 = mn1;

            float s0 = 0.0f, s1 = 0.0f;
#pragma unroll
            for (int na = 0; na < 8; na++) {
                sc[na][0] = __expf(sc[na][0] - m0);
                sc[na][1] = __expf(sc[na][1] - m0);
                sc[na][2] = __expf(sc[na][2] - m1);
                sc[na][3] = __expf(sc[na][3] - m1);
                s0 += sc[na][0] + sc[na][1];
                s1 += sc[na][2] + sc[na][3];
            }
            s0 += __shfl_xor_sync(0xffffffffu, s0, 1);
            s0 += __shfl_xor_sync(0xffffffffu, s0, 2);
            s1 += __shfl_xor_sync(0xffffffffu, s1, 1);
            s1 += __shfl_xor_sync(0xffffffffu, s1, 2);
            l0 = l0 * scl0 + s0;
            l1 = l1 * scl1 + s1;

#pragma unroll
            for (int na = 0; na < 8; na++) {
                oc[na][0] *= scl0; oc[na][1] *= scl0;
                oc[na][2] *= scl1; oc[na][3] *= scl1;
            }
        }

        // ---- O += P V ----
#pragma unroll
        for (int ks = 0; ks < 4; ks++) {
            unsigned a0 = packh2(sc[2 * ks][0],     sc[2 * ks][1]);
            unsigned a1 = packh2(sc[2 * ks][2],     sc[2 * ks][3]);
            unsigned a2 = packh2(sc[2 * ks + 1][0], sc[2 * ks + 1][1]);
            unsigned a3 = packh2(sc[2 * ks + 1][2], sc[2 * ks + 1][3]);
#pragma unroll
            for (int na = 0; na < 8; na++) {
                uint2 bv = *(const uint2*)(cV + (((na * 8 + lr) * DD
                              + ((ks ^ lrm) << 4) + 4 * lc) * 2));
                mma_fp16(oc[na], a0, a1, a2, a3, bv.x, bv.y);
            }
        }

        __syncthreads();     // all reads of stage s finished

        // ---- refill stage s with tile t+2 ----
        if (t + 2 < t1) {
            const unsigned base = smb + s * SSZ_B;
            const char* gk = (const char*)g_Hk + (size_t)(t + 2) * KBYTES;
            const char* gv = (const char*)g_Hv + (size_t)(t + 2) * VBYTES;
            cpa16(base + tid * 16,                  gk + tid * 16);
            cpa16(base + (tid + NT) * 16,           gk + (tid + NT) * 16);
            cpa16(base + KBYTES + tid * 16,         gv + tid * 16);
            cpa16(base + KBYTES + (tid + NT) * 16,  gv + (tid + NT) * 16);
#pragma unroll
            for (int ii = 0; ii < 8; ii++) {
                int g = tid + ii * NT;
                int row = g >> 4, c = g & 15;
                cpa16(base + KBYTES + VBYTES + row * 256 + ((c ^ (row & 15)) << 4),
                      A + (size_t)(qbase + row) * NN + (t + 2) * BN + c * 4);
            }
        }
        cpa_commit();
    }

    // ---- write partials (plane si) ----
    float* Op = g_Op + (size_t)si * NN * DD;
#pragma unroll
    for (int na = 0; na < 8; na++) {
        int c0 = na * 8 + 2 * lc;
        *(float2*)&Op[(size_t)r0 * DD + c0]       = make_float2(oc[na][0], oc[na][1]);
        *(float2*)&Op[(size_t)(r0 + 8) * DD + c0] = make_float2(oc[na][2], oc[na][3]);
    }
    if (lc == 0) {
        g_mp[si * NN + r0]     = m0;
        g_mp[si * NN + r0 + 8] = m1;
        g_lp[si * NN + r0]     = l0;
        g_lp[si * NN + r0 + 8] = l1;
    }
}

// ---------------------------------------------------------------------------
// Kernel 3: m-aware merge (float4): 5-way for rows < 5120, 4-way above.
// ---------------------------------------------------------------------------
__global__ void merge_kernel(float* __restrict__ Out) {
    int i4  = blockIdx.x * 256 + threadIdx.x;
    int idx = i4 * 4;
    int row = idx >> 6;
    const int ns = (row < 5120) ? 5 : 4;

    float M = -CUDART_INF_F;
#pragma unroll
    for (int s = 0; s < NSPLIT; s++)
        if (s < ns) M = fmaxf(M, g_mp[s * NN + row]);

    float denom = 0.0f;
    float ax = 0.0f, ay = 0.0f, az = 0.0f, aw = 0.0f;
#pragma unroll
    for (int s = 0; s < NSPLIT; s++) {
        if (s < ns) {
            float wgt = __expf(g_mp[s * NN + row] - M);
            denom += wgt * g_lp[s * NN + row];
            float4 o = *(const float4*)&g_Op[(size_t)s * NN * DD + idx];
            ax += wgt * o.x; ay += wgt * o.y;
            az += wgt * o.z; aw += wgt * o.w;
        }
    }
    float inv = 1.0f / denom;
    float4 o;
    o.x = fmaxf(ax * inv, 0.0f);
    o.y = fmaxf(ay * inv, 0.0f);
    o.z = fmaxf(az * inv, 0.0f);
    o.w = fmaxf(aw * inv, 0.0f);
    *(float4*)&Out[idx] = o;
}

// ---------------------------------------------------------------------------
extern "C" void kernel_launch(void* const* d_in, const int* in_sizes, int n_in,
                              void* d_out, int out_size) {
    const float* X = (const float*)d_in[0];
    const int*   A = (const int*)  d_in[1];
    const float* W = (const float*)d_in[2];
    const float* b = (const float*)d_in[3];
    float* Out = (float*)d_out;

    const int smem_bytes = STAGES * SSZ_B;        // 98304
    static bool attr_set = false;
    if (!attr_set) {
        cudaFuncSetAttribute(flash_mma,
                             cudaFuncAttributeMaxDynamicSharedMemorySize,
                             smem_bytes);
        attr_set = true;
    }

    h_kernel<<<NN / 8, 256>>>(X, W, b);
    flash_mma<<<296, NT, smem_bytes>>>(A);
    merge_kernel<<<NN * DD / 4 / 256, 256>>>(Out);
}